// round 3
// baseline (speedup 1.0000x reference)
#include <cuda_runtime.h>

// ---------------------------------------------------------------------------
// CurvatureLoss3D on GB300 (sm_103a)
// phi: [2, 1, 192, 192, 192] fp32  ->  scalar fp32
// Single fused pass: 9 finite-difference stencils + curvature penalty +
// 27-point min/max zero-crossing mask + global masked-mean reduction.
//
// Strategy: register sliding window along z. Each thread computes 4
// consecutive x-outputs on one y-line, holding a 3(z) x 3(y) x 6(x) fp32
// window in registers. Per z-step it loads ONE new plane (3 rows, coalesced
// float4+float2, 16B aligned) and computes 4 outputs entirely from registers.
// Deterministic 2-kernel reduction via __device__ partial arrays (no atomics,
// no allocation, graph-capturable).
// ---------------------------------------------------------------------------

#define WW 192
#define ZS (192 * 192)          // plane stride
#define NVOL (192 * 192 * 192)  // batch stride
#define EPSF 1e-8f
// 1 / (CURV_THRESH + EPS)^2 computed in double, rounded to float
#define INV_T2 3.9999998f

#define NCHUNK 48        // x-chunks per line (4 outputs each, covers x=1..190 +2 masked)
#define ROWS_PER_BLK 4   // y-lines per block
#define NTHREADS (NCHUNK * ROWS_PER_BLK)  // 192
#define ZSPLIT 6
#define ZPER 32          // z-centers per block (last block: 30)
#define NBLOCKS (NCHUNK_GRID * ZSPLIT * 2)
#define NCHUNK_GRID 48   // y-groups: ceil(190/4) = 48
#define TOTAL_BLOCKS (48 * ZSPLIT * 2)    // 576

static __device__ double    d_part_pen[TOTAL_BLOCKS];
static __device__ long long d_part_cnt[TOTAL_BLOCKS];

__device__ __forceinline__ float approx_sqrt(float x) {
    float r; asm("sqrt.approx.f32 %0, %1;" : "=f"(r) : "f"(x)); return r;
}
__device__ __forceinline__ float approx_rcp(float x) {
    float r; asm("rcp.approx.f32 %0, %1;" : "=f"(r) : "f"(x)); return r;
}

// Load one z-plane slice: 3 rows (y-1..y+1) x 6 x-values into registers.
// rowbase points at (z, y-1, 4*cid). float4 is 16B aligned (4*cid floats),
// float2 at +4 floats is 8B aligned. Last chunk skips the tail (would run
// past the row / array end); its two tail slots feed only masked outputs.
__device__ __forceinline__ void load_plane(const float* __restrict__ rowbase,
                                           float (&P)[3][6], bool last_chunk) {
#pragma unroll
    for (int r = 0; r < 3; r++) {
        const float* p = rowbase + r * WW;
        float4 v = *reinterpret_cast<const float4*>(p);
        P[r][0] = v.x; P[r][1] = v.y; P[r][2] = v.z; P[r][3] = v.w;
        if (!last_chunk) {
            float2 w = *reinterpret_cast<const float2*>(p + 4);
            P[r][4] = w.x; P[r][5] = w.y;
        } else {
            P[r][4] = 0.0f; P[r][5] = 0.0f;
        }
    }
}

// One z-step: planes A(z-1), B(z), C(z+1); computes 4 x-outputs.
__device__ __forceinline__ void do_step(const float (&A)[3][6],
                                        const float (&B)[3][6],
                                        const float (&C)[3][6],
                                        float& acc_pen, int& acc_cnt,
                                        int xvalid) {
    // per-x-column min/max over the 9 (z,y) values, shared by the 4 outputs
    float colmn[6], colmx[6];
#pragma unroll
    for (int i = 0; i < 6; i++) {
        float a0 = A[0][i], a1 = A[1][i], a2 = A[2][i];
        float b0 = B[0][i], b1 = B[1][i], b2 = B[2][i];
        float c0 = C[0][i], c1 = C[1][i], c2 = C[2][i];
        float mn = fminf(fminf(fminf(a0, a1), fminf(a2, b0)),
                         fminf(fminf(b1, b2), fminf(fminf(c0, c1), c2)));
        float mx = fmaxf(fmaxf(fmaxf(a0, a1), fmaxf(a2, b0)),
                         fmaxf(fmaxf(b1, b2), fmaxf(fmaxf(c0, c1), c2)));
        colmn[i] = mn; colmx[i] = mx;
    }

#pragma unroll
    for (int j = 0; j < 4; j++) {
        if (j < xvalid) {
            float c   = B[1][j + 1];
            float gx  = 0.5f * (B[1][j + 2] - B[1][j]);
            float gy  = 0.5f * (B[2][j + 1] - B[0][j + 1]);
            float gz  = 0.5f * (C[1][j + 1] - A[1][j + 1]);
            float hxx = B[1][j] + B[1][j + 2] - 2.0f * c;
            float hyy = B[0][j + 1] + B[2][j + 1] - 2.0f * c;
            float hzz = A[1][j + 1] + C[1][j + 1] - 2.0f * c;
            float hxy = 0.25f * ((B[0][j] + B[2][j + 2]) - (B[0][j + 2] + B[2][j]));
            float hxz = 0.25f * ((A[1][j] + C[1][j + 2]) - (A[1][j + 2] + C[1][j]));
            float hyz = 0.25f * ((A[0][j + 1] + C[2][j + 1]) - (A[2][j + 1] + C[0][j + 1]));

            float gx2 = gx * gx, gy2 = gy * gy, gz2 = gz * gz;
            float s    = gx2 + gy2 + gz2 + EPSF;
            float mag  = approx_sqrt(s);
            float mag3 = mag * s;                 // mag^3 since s = mag^2
            float inv3 = approx_rcp(mag3 + EPSF);
            float invm = approx_rcp(mag + EPSF);

            float cross = gx * gy * hxy + gx * gz * hxz + gy * gz * hyz;
            float syz = hyy + hzz, sxz = hxx + hzz, sxy = hxx + hyy;
            float mean_c = (gx2 * syz + gy2 * sxz + gz2 * sxy - 2.0f * cross) * inv3;
            float lap    = (hxx + syz) * invm;
            float quad   = (gx2 * hxx + gy2 * hyy + gz2 * hzz + 2.0f * cross) * inv3;
            float gauss  = lap - quad;
            float k1  = mean_c + approx_sqrt(fabsf(mean_c * mean_c - gauss) + EPSF);
            float pen = fmaxf(fmaf(k1 * k1, INV_T2, -1.0f), 0.0f);

            float mn = fminf(fminf(colmn[j], colmn[j + 1]), colmn[j + 2]);
            float mx = fmaxf(fmaxf(colmx[j], colmx[j + 1]), colmx[j + 2]);
            if (mn * mx < 0.0f) { acc_pen += pen; acc_cnt += 1; }
        }
    }
}

__global__ void __launch_bounds__(NTHREADS, 2)
curvature_kernel(const float* __restrict__ phi) {
    const int tid = threadIdx.x;
    const int cid = tid % NCHUNK;       // x-chunk id
    const int ry  = tid / NCHUNK;       // row within y-group
    const int n   = blockIdx.z;
    const int y   = 1 + blockIdx.x * ROWS_PER_BLK + ry;   // center y
    const int zs  = 1 + blockIdx.y * ZPER;
    const int ze  = min(zs + ZPER - 1, 190);
    const bool active = (y <= 190);
    const bool last   = (cid == NCHUNK - 1);
    const int xvalid  = last ? 2 : 4;   // last chunk: centers 189,190 valid

    float acc_pen = 0.0f;
    int   acc_cnt = 0;

    if (active) {
        const float* base = phi + (size_t)n * NVOL + (size_t)(y - 1) * WW + 4 * cid;
        float A[3][6], Bp[3][6], Cp[3][6];
        load_plane(base + (size_t)(zs - 1) * ZS, A,  last);
        load_plane(base + (size_t)zs       * ZS, Bp, last);

        int zc = zs;
        for (; zc + 2 <= ze; zc += 3) {
            load_plane(base + (size_t)(zc + 1) * ZS, Cp, last);
            do_step(A, Bp, Cp, acc_pen, acc_cnt, xvalid);
            load_plane(base + (size_t)(zc + 2) * ZS, A, last);
            do_step(Bp, Cp, A, acc_pen, acc_cnt, xvalid);
            load_plane(base + (size_t)(zc + 3) * ZS, Bp, last);
            do_step(Cp, A, Bp, acc_pen, acc_cnt, xvalid);
        }
        if (zc <= ze) {
            load_plane(base + (size_t)(zc + 1) * ZS, Cp, last);
            do_step(A, Bp, Cp, acc_pen, acc_cnt, xvalid);
            zc++;
            if (zc <= ze) {
                load_plane(base + (size_t)(zc + 1) * ZS, A, last);
                do_step(Bp, Cp, A, acc_pen, acc_cnt, xvalid);
            }
        }
    }

    // block reduction (deterministic)
    __shared__ double spen[NTHREADS];
    __shared__ int    scnt[NTHREADS];
    spen[tid] = (double)acc_pen;
    scnt[tid] = acc_cnt;
    __syncthreads();
    if (tid < 64) {
        spen[tid] += spen[tid + 64] + spen[tid + 128];
        scnt[tid] += scnt[tid + 64] + scnt[tid + 128];
    }
    __syncthreads();
    if (tid < 32) {
        double p = spen[tid] + spen[tid + 32];
        int    q = scnt[tid] + scnt[tid + 32];
#pragma unroll
        for (int o = 16; o > 0; o >>= 1) {
            p += __shfl_down_sync(0xffffffffu, p, o);
            q += __shfl_down_sync(0xffffffffu, q, o);
        }
        if (tid == 0) {
            int bid = (blockIdx.z * gridDim.y + blockIdx.y) * gridDim.x + blockIdx.x;
            d_part_pen[bid] = p;
            d_part_cnt[bid] = (long long)q;
        }
    }
}

__global__ void finalize_kernel(float* __restrict__ out) {
    __shared__ double    sp[192];
    __shared__ long long sc[192];
    const int tid = threadIdx.x;
    double p = 0.0; long long c = 0;
    for (int i = tid; i < TOTAL_BLOCKS; i += 192) {
        p += d_part_pen[i];
        c += d_part_cnt[i];
    }
    sp[tid] = p; sc[tid] = c;
    __syncthreads();
    if (tid < 64) {
        sp[tid] += sp[tid + 64] + sp[tid + 128];
        sc[tid] += sc[tid + 64] + sc[tid + 128];
    }
    __syncthreads();
    if (tid < 32) {
        double    pp = sp[tid] + sp[tid + 32];
        long long cc = sc[tid] + sc[tid + 32];
#pragma unroll
        for (int o = 16; o > 0; o >>= 1) {
            pp += __shfl_down_sync(0xffffffffu, pp, o);
            cc += __shfl_down_sync(0xffffffffu, cc, o);
        }
        if (tid == 0)
            out[0] = (float)(pp / ((double)cc + 1e-8));
    }
}

extern "C" void kernel_launch(void* const* d_in, const int* in_sizes, int n_in,
                              void* d_out, int out_size) {
    const float* phi = (const float*)d_in[0];
    float* out = (float*)d_out;
    dim3 grid(NCHUNK_GRID, ZSPLIT, 2);
    curvature_kernel<<<grid, NTHREADS>>>(phi);
    finalize_kernel<<<1, 192>>>(out);
}

// round 6
// speedup vs baseline: 1.9517x; 1.9517x over previous
#include <cuda_runtime.h>

// ---------------------------------------------------------------------------
// CurvatureLoss3D on GB300 (sm_103a) — packed f32x2 version, fused finalize.
// phi: [2, 1, 192, 192, 192] fp32  ->  scalar fp32
//
// FMA-pipe bound kernel: process the 4 x-outputs per thread as 2 f32x2 pairs
// using sm_103a packed fp32 (add/sub/mul/fma.rn.f32x2). Sliding register
// window along z stored as f32x2 pairs (even pairs free from float4 loads,
// odd pairs built once per plane load). Stencil scale factors (0.5, 0.25)
// folded algebraically; rsqrt replaces sqrt+2*rcp (2 MUFU/output).
// Finalize fused via wrap-around atomicInc last-block reduction
// (deterministic, self-resetting, graph-capturable).
// ---------------------------------------------------------------------------

#define WW 192
#define ZS (192 * 192)
#define NVOL (192 * 192 * 192)
#define EPSF 1e-8f
#define INV_T2 3.9999998f     // 1/(0.5+1e-8)^2

#define NCHUNK 48             // x-chunks (4 outputs each) per line
#define ROWS_PER_BLK 4
#define NTHREADS (NCHUNK * ROWS_PER_BLK)   // 192
#define ZSPLIT 6
#define ZPER 32
#define NCHUNK_GRID 48        // y-groups
#define TOTAL_BLOCKS (NCHUNK_GRID * ZSPLIT * 2)  // 576

static __device__ double d_part_pen[TOTAL_BLOCKS];
static __device__ int    d_part_cnt[TOTAL_BLOCKS];
static __device__ unsigned int d_done;   // zero-init; wraps back to 0 each launch

// ---------------- packed f32x2 helpers (double as 64-bit carrier) ----------
__device__ __forceinline__ double f2(float lo, float hi) {
    return __hiloint2double(__float_as_int(hi), __float_as_int(lo));
}
__device__ __forceinline__ float f2lo(double v) { return __int_as_float(__double2loint(v)); }
__device__ __forceinline__ float f2hi(double v) { return __int_as_float(__double2hiint(v)); }

__device__ __forceinline__ double f2add(double a, double b) {
    double d; asm("add.rn.f32x2 %0, %1, %2;" : "=d"(d) : "d"(a), "d"(b)); return d;
}
__device__ __forceinline__ double f2sub(double a, double b) {
    double d; asm("sub.rn.f32x2 %0, %1, %2;" : "=d"(d) : "d"(a), "d"(b)); return d;
}
__device__ __forceinline__ double f2mul(double a, double b) {
    double d; asm("mul.rn.f32x2 %0, %1, %2;" : "=d"(d) : "d"(a), "d"(b)); return d;
}
__device__ __forceinline__ double f2fma(double a, double b, double c) {
    double d; asm("fma.rn.f32x2 %0, %1, %2, %3;" : "=d"(d) : "d"(a), "d"(b), "d"(c)); return d;
}
__device__ __forceinline__ float approx_sqrt(float x) {
    float r; asm("sqrt.approx.f32 %0, %1;" : "=f"(r) : "f"(x)); return r;
}
__device__ __forceinline__ float approx_rsqrt(float x) {
    float r; asm("rsqrt.approx.f32 %0, %1;" : "=f"(r) : "f"(x)); return r;
}

// One y-row of one z-plane: 6 window columns as 3 even pairs + 2 odd pairs.
struct Row { double e[3]; double o[2]; };
struct Plane { Row r[3]; };

// Load 3 rows (y-1..y+1) of one z-plane. float4 16B-aligned, float2 8B.
__device__ __forceinline__ void load_plane(const float* __restrict__ rowbase,
                                           Plane& P, bool last_chunk) {
#pragma unroll
    for (int r = 0; r < 3; r++) {
        const float* p = rowbase + r * WW;
        float4 v = *reinterpret_cast<const float4*>(p);
        float w0 = 0.0f, w1 = 0.0f;
        if (!last_chunk) {
            float2 w = *reinterpret_cast<const float2*>(p + 4);
            w0 = w.x; w1 = w.y;
        }
        P.r[r].e[0] = f2(v.x, v.y);
        P.r[r].e[1] = f2(v.z, v.w);
        P.r[r].e[2] = f2(w0, w1);
        P.r[r].o[0] = f2(v.y, v.z);
        P.r[r].o[1] = f2(v.w, w0);
    }
}

// min/max of 9 packed values, per half (lo -> col 2e, hi -> col 2e+1).
__device__ __forceinline__ void minmax9(double a, double b, double c,
                                        double d, double e, double f,
                                        double g, double h, double i,
                                        float& mnl, float& mxl,
                                        float& mnh, float& mxh) {
    float a0 = f2lo(a), a1 = f2lo(b), a2 = f2lo(c), a3 = f2lo(d), a4 = f2lo(e),
          a5 = f2lo(f), a6 = f2lo(g), a7 = f2lo(h), a8 = f2lo(i);
    mnl = fminf(fminf(fminf(fminf(a0, a1), fminf(a2, a3)),
                      fminf(fminf(a4, a5), fminf(a6, a7))), a8);
    mxl = fmaxf(fmaxf(fmaxf(fmaxf(a0, a1), fmaxf(a2, a3)),
                      fmaxf(fmaxf(a4, a5), fmaxf(a6, a7))), a8);
    float b0 = f2hi(a), b1 = f2hi(b), b2 = f2hi(c), b3 = f2hi(d), b4 = f2hi(e),
          b5 = f2hi(f), b6 = f2hi(g), b7 = f2hi(h), b8 = f2hi(i);
    mnh = fminf(fminf(fminf(fminf(b0, b1), fminf(b2, b3)),
                      fminf(fminf(b4, b5), fminf(b6, b7))), b8);
    mxh = fmaxf(fmaxf(fmaxf(fmaxf(b0, b1), fmaxf(b2, b3)),
                      fmaxf(fmaxf(b4, b5), fmaxf(b6, b7))), b8);
}

// Curvature algebra for one output pair p (p=0: outputs j=0,1; p=1: j=2,3),
// fully packed. Deferred scaling: G = 2*grad, Hm = 4*mixed-hessian.
//   r    = rsqrt(Gx^2+Gy^2+Gz^2 + 4*EPS)            (= 1/(2*mag))
//   mean = r^3 * (2*QS - CR)
//   gauss= 2*r*L - r^3 * (2*QH + CR)
template <int P>
__device__ __forceinline__ void pair_compute(const Plane& A, const Plane& B,
                                             const Plane& C,
                                             double C_M2, double C_EPS4,
                                             float& mc_lo, float& mc_hi,
                                             float& d_lo, float& d_hi) {
    const double c   = B.r[1].o[P];
    const double Gx  = f2sub(B.r[1].e[P + 1], B.r[1].e[P]);
    const double Gy  = f2sub(B.r[2].o[P],     B.r[0].o[P]);
    const double Gz  = f2sub(C.r[1].o[P],     A.r[1].o[P]);
    const double hxx = f2fma(c, C_M2, f2add(B.r[1].e[P], B.r[1].e[P + 1]));
    const double hyy = f2fma(c, C_M2, f2add(B.r[0].o[P], B.r[2].o[P]));
    const double hzz = f2fma(c, C_M2, f2add(A.r[1].o[P], C.r[1].o[P]));
    const double Hxy = f2sub(f2add(B.r[0].e[P], B.r[2].e[P + 1]),
                             f2add(B.r[0].e[P + 1], B.r[2].e[P]));
    const double Hxz = f2sub(f2add(A.r[1].e[P], C.r[1].e[P + 1]),
                             f2add(A.r[1].e[P + 1], C.r[1].e[P]));
    const double Hyz = f2sub(f2add(A.r[0].o[P], C.r[2].o[P]),
                             f2add(A.r[2].o[P], C.r[0].o[P]));

    const double Gx2 = f2mul(Gx, Gx);
    const double Gy2 = f2mul(Gy, Gy);
    const double Gz2 = f2mul(Gz, Gz);
    const double Qe  = f2fma(Gz, Gz, f2fma(Gy, Gy, f2fma(Gx, Gx, C_EPS4)));

    const double Syz = f2add(hyy, hzz);
    const double Sxz = f2add(hxx, hzz);
    const double Sxy = f2add(hxx, hyy);
    const double L   = f2add(hxx, Syz);

    const double QS = f2fma(Gz2, Sxy, f2fma(Gy2, Sxz, f2mul(Gx2, Syz)));
    const double QH = f2fma(Gz2, hzz, f2fma(Gy2, hyy, f2mul(Gx2, hxx)));
    const double GxGy = f2mul(Gx, Gy);
    const double GxGz = f2mul(Gx, Gz);
    const double GyGz = f2mul(Gy, Gz);
    const double CR = f2fma(GyGz, Hyz, f2fma(GxGz, Hxz, f2mul(GxGy, Hxy)));

    const double r  = f2(approx_rsqrt(f2lo(Qe)), approx_rsqrt(f2hi(Qe)));
    const double r3 = f2mul(f2mul(r, r), r);

    const double mc    = f2mul(r3, f2sub(f2add(QS, QS), CR));
    const double quad  = f2mul(r3, f2add(f2add(QH, QH), CR));
    const double rL    = f2mul(r, L);
    const double gauss = f2sub(f2add(rL, rL), quad);
    const double disc  = f2sub(f2mul(mc, mc), gauss);

    mc_lo = f2lo(mc); mc_hi = f2hi(mc);
    d_lo  = f2lo(disc); d_hi = f2hi(disc);
}

__device__ __forceinline__ void do_step(const Plane& A, const Plane& B,
                                        const Plane& C,
                                        double C_M2, double C_EPS4,
                                        float& acc_pen, int& acc_cnt,
                                        int xvalid) {
    // per-column min/max over the 27-neighborhood z/y extent
    float colmn[6], colmx[6];
#pragma unroll
    for (int e = 0; e < 3; e++) {
        minmax9(A.r[0].e[e], A.r[1].e[e], A.r[2].e[e],
                B.r[0].e[e], B.r[1].e[e], B.r[2].e[e],
                C.r[0].e[e], C.r[1].e[e], C.r[2].e[e],
                colmn[2 * e], colmx[2 * e], colmn[2 * e + 1], colmx[2 * e + 1]);
    }

    float mcs[4], ds[4];
    pair_compute<0>(A, B, C, C_M2, C_EPS4, mcs[0], mcs[1], ds[0], ds[1]);
    pair_compute<1>(A, B, C, C_M2, C_EPS4, mcs[2], mcs[3], ds[2], ds[3]);

#pragma unroll
    for (int j = 0; j < 4; j++) {
        float t   = approx_sqrt(fabsf(ds[j]) + EPSF);
        float k1  = mcs[j] + t;
        float pen = fmaxf(fmaf(k1 * k1, INV_T2, -1.0f), 0.0f);
        float mn  = fminf(fminf(colmn[j], colmn[j + 1]), colmn[j + 2]);
        float mx  = fmaxf(fmaxf(colmx[j], colmx[j + 1]), colmx[j + 2]);
        if (j < xvalid && (mn * mx < 0.0f)) { acc_pen += pen; acc_cnt += 1; }
    }
}

__global__ void __launch_bounds__(NTHREADS, 2)
curvature_kernel(const float* __restrict__ phi, float* __restrict__ out) {
    const int tid = threadIdx.x;
    const int cid = tid % NCHUNK;
    const int ry  = tid / NCHUNK;
    const int n   = blockIdx.z;
    const int y   = 1 + blockIdx.x * ROWS_PER_BLK + ry;
    const int zs  = 1 + blockIdx.y * ZPER;
    const int ze  = min(zs + ZPER - 1, 190);
    const bool active = (y <= 190);
    const bool last   = (cid == NCHUNK - 1);
    const int xvalid  = last ? 2 : 4;

    const double C_M2   = f2(-2.0f, -2.0f);
    const double C_EPS4 = f2(4e-8f, 4e-8f);

    float acc_pen = 0.0f;
    int   acc_cnt = 0;

    if (active) {
        const float* base = phi + (size_t)n * NVOL + (size_t)(y - 1) * WW + 4 * cid;
        Plane A, B, C;
        load_plane(base + (size_t)(zs - 1) * ZS, A, last);
        load_plane(base + (size_t)zs       * ZS, B, last);

        int zc = zs;
        for (; zc + 2 <= ze; zc += 3) {
            load_plane(base + (size_t)(zc + 1) * ZS, C, last);
            do_step(A, B, C, C_M2, C_EPS4, acc_pen, acc_cnt, xvalid);
            load_plane(base + (size_t)(zc + 2) * ZS, A, last);
            do_step(B, C, A, C_M2, C_EPS4, acc_pen, acc_cnt, xvalid);
            load_plane(base + (size_t)(zc + 3) * ZS, B, last);
            do_step(C, A, B, C_M2, C_EPS4, acc_pen, acc_cnt, xvalid);
        }
        if (zc <= ze) {
            load_plane(base + (size_t)(zc + 1) * ZS, C, last);
            do_step(A, B, C, C_M2, C_EPS4, acc_pen, acc_cnt, xvalid);
            zc++;
            if (zc <= ze) {
                load_plane(base + (size_t)(zc + 1) * ZS, A, last);
                do_step(B, C, A, C_M2, C_EPS4, acc_pen, acc_cnt, xvalid);
            }
        }
    }

    // ---- block reduction (deterministic) ----
    __shared__ double spen[NTHREADS];
    __shared__ int    scnt[NTHREADS];
    __shared__ int    s_last;
    spen[tid] = (double)acc_pen;
    scnt[tid] = acc_cnt;
    __syncthreads();
    if (tid < 64) {
        spen[tid] += spen[tid + 64] + spen[tid + 128];
        scnt[tid] += scnt[tid + 64] + scnt[tid + 128];
    }
    __syncthreads();
    if (tid < 32) {
        double p = spen[tid] + spen[tid + 32];
        int    q = scnt[tid] + scnt[tid + 32];
#pragma unroll
        for (int o = 16; o > 0; o >>= 1) {
            p += __shfl_down_sync(0xffffffffu, p, o);
            q += __shfl_down_sync(0xffffffffu, q, o);
        }
        if (tid == 0) {
            int bid = (blockIdx.z * gridDim.y + blockIdx.y) * gridDim.x + blockIdx.x;
            d_part_pen[bid] = p;
            d_part_cnt[bid] = q;
            __threadfence();
            unsigned int old = atomicInc(&d_done, TOTAL_BLOCKS - 1);  // wraps to 0
            s_last = (old == TOTAL_BLOCKS - 1) ? 1 : 0;
        }
    }
    __syncthreads();

    // ---- fused finalize: the last block reduces all partials (fixed order) ----
    if (s_last) {
        double p = 0.0; int c = 0;
        for (int i = tid; i < TOTAL_BLOCKS; i += NTHREADS) {
            p += __ldcg(&d_part_pen[i]);
            c += __ldcg(&d_part_cnt[i]);
        }
        spen[tid] = p; scnt[tid] = c;
        __syncthreads();
        if (tid < 64) {
            spen[tid] += spen[tid + 64] + spen[tid + 128];
            scnt[tid] += scnt[tid + 64] + scnt[tid + 128];
        }
        __syncthreads();
        if (tid < 32) {
            double pp = spen[tid] + spen[tid + 32];
            int    cc = scnt[tid] + scnt[tid + 32];
#pragma unroll
            for (int o = 16; o > 0; o >>= 1) {
                pp += __shfl_down_sync(0xffffffffu, pp, o);
                cc += __shfl_down_sync(0xffffffffu, cc, o);
            }
            if (tid == 0)
                out[0] = (float)(pp / ((double)cc + 1e-8));
        }
    }
}

extern "C" void kernel_launch(void* const* d_in, const int* in_sizes, int n_in,
                              void* d_out, int out_size) {
    const float* phi = (const float*)d_in[0];
    float* out = (float*)d_out;
    dim3 grid(NCHUNK_GRID, ZSPLIT, 2);
    curvature_kernel<<<grid, NTHREADS>>>(phi, out);
}